// round 5
// baseline (speedup 1.0000x reference)
#include <cuda_runtime.h>

// SQEmbedding fused kernel for GB300 (sm_103a).  B=8,T=4096,D=64,M=1024,N=32768.
// Inputs: x(B,D,T) f32, embedding(M,D) f32, log_var_q f32[1], gumbels(N,M) f32,
//         temperature f32[1].  Output: quantized(B,D,T) + loss + perplexity.

#define BB 8
#define TT 4096
#define DD 64
#define MM 1024
#define NN (BB * TT)
#define ROWS 32
#define NTILES (NN / ROWS)      // 1024
#define THREADS 512
#define NWARP (THREADS / 32)    // 16
#define CHUNK 128
#define NCH (MM / CHUNK)        // 8
#define XS 68                    // x row stride (16B-aligned rows for float4)
#define ES 65                    // e row stride (conflict-free scalar r/w)
#define QS 66

#define SMEM_FLOATS (ROWS*XS + ROWS*MM + 2*CHUNK*ES + 2*ROWS*QS + 3*ROWS + NWARP)
#define SMEM_BYTES (SMEM_FLOATS * 4)

__device__ float g_e2[MM];          // ||e_m||^2
__device__ int   g_hist[MM];        // hard-assignment histogram
__device__ float g_partial[NTILES]; // per-CTA loss partials (deterministic)

// ---------------------------------------------------------------------------
__global__ void prep_kernel(const float* __restrict__ emb) {
    int m = blockIdx.x * 8 + (threadIdx.x >> 5);
    int lane = threadIdx.x & 31;
    if (m < MM) {
        float2 v = ((const float2*)(emb + m * DD))[lane];
        float s = fmaf(v.x, v.x, v.y * v.y);
#pragma unroll
        for (int off = 16; off; off >>= 1) s += __shfl_xor_sync(~0u, s, off);
        if (lane == 0) { g_e2[m] = s; g_hist[m] = 0; }
    }
}

// ---------------------------------------------------------------------------
__global__ __launch_bounds__(THREADS, 1)
void sqembed_main(const float* __restrict__ x,
                  const float* __restrict__ emb,
                  const float* __restrict__ lvq,
                  const float* __restrict__ gum,
                  const float* __restrict__ temp,
                  float* __restrict__ out) {
    extern __shared__ float smem[];
    float* s_x   = smem;                       // ROWS*XS
    float* s_lg  = s_x + ROWS * XS;            // ROWS*MM  (logits -> w -> ew)
    float* s_eb  = s_lg + ROWS * MM;           // 2 * CHUNK*ES (double buffer)
    float* s_q   = s_eb + 2 * CHUNK * ES;      // 2*ROWS*QS (m-half partials)
    float* s_x2  = s_q + 2 * ROWS * QS;        // ROWS
    float* s_ent = s_x2 + ROWS;                // ROWS
    float* s_inv = s_ent + ROWS;               // ROWS (1/s1 per row)
    float* s_red = s_inv + ROWS;               // NWARP

    const int tid = threadIdx.x, lane = tid & 31, warp = tid >> 5;
    const int n0 = blockIdx.x * ROWS;
    const int b = n0 / TT, t0 = n0 % TT;
    const float prec = __expf(-lvq[0]);
    const float hp = 0.5f * prec;
    const float invT = 1.0f / temp[0];

    // ---- P0: x tile (coalesced along t) + e-chunk0 register prefetch ----
#pragma unroll
    for (int i = tid; i < ROWS * DD; i += THREADS) {
        int r = i & 31, d = i >> 5;
        s_x[r * XS + d] = x[(b * DD + d) * TT + t0 + r];
    }
    float pf[16];
#pragma unroll
    for (int k = 0; k < 16; ++k) pf[k] = emb[tid + THREADS * k];
    __syncthreads();
    {   // per-row ||x||^2 (16 threads per row, float4)
        int r = tid >> 4, c = tid & 15;
        float4 v = *(const float4*)&s_x[r * XS + c * 4];
        float s = fmaf(v.x, v.x, fmaf(v.y, v.y, fmaf(v.z, v.z, v.w * v.w)));
#pragma unroll
        for (int off = 8; off; off >>= 1) s += __shfl_down_sync(~0u, s, off, 16);
        if (c == 0) s_x2[r] = s;
    }

    // ---- GEMM1: logits = prec*(x.e) - hp*(|x|^2+|e|^2)   (lane <-> m) ----
    const int rg1 = (warp & 3) * 8;     // 8 rows
    const int mg1 = (warp >> 2) * 32;   // 32 m per warp (lane-mapped)
    for (int ch = 0; ch < NCH; ++ch) {
        float* eb = s_eb + (ch & 1) * (CHUNK * ES);
#pragma unroll
        for (int k = 0; k < 16; ++k) {
            int idx = tid + THREADS * k;
            eb[(idx >> 6) * ES + (idx & 63)] = pf[k];   // conflict-free STS
        }
        if (ch + 1 < NCH) {
            const float* src = emb + (ch + 1) * (CHUNK * DD);
#pragma unroll
            for (int k = 0; k < 16; ++k) pf[k] = src[tid + THREADS * k];
        }
        __syncthreads();
        float acc[8] = {0, 0, 0, 0, 0, 0, 0, 0};
        const float* erow = eb + (mg1 + lane) * ES;
#pragma unroll
        for (int dw = 0; dw < 16; ++dw) {
            float e0 = erow[dw * 4 + 0], e1 = erow[dw * 4 + 1];
            float e2v = erow[dw * 4 + 2], e3 = erow[dw * 4 + 3];
#pragma unroll
            for (int r = 0; r < 8; ++r) {
                float4 xv = *(const float4*)&s_x[(rg1 + r) * XS + dw * 4];
                acc[r] = fmaf(xv.w, e3, fmaf(xv.z, e2v,
                          fmaf(xv.y, e1, fmaf(xv.x, e0, acc[r]))));
            }
        }
        int m = ch * CHUNK + mg1 + lane;
        float en = g_e2[m];
#pragma unroll
        for (int r = 0; r < 8; ++r)
            s_lg[(rg1 + r) * MM + m] = prec * acc[r] - hp * (s_x2[rg1 + r] + en);
    }
    // prefetch GEMM2 chunk 0 now; softmax hides the global latency
#pragma unroll
    for (int k = 0; k < 16; ++k) pf[k] = emb[tid + THREADS * k];
    __syncthreads();

    // ---- Softmax: warp owns rows 2w, 2w+1; all exps independent ----
#pragma unroll 1
    for (int rr = 0; rr < 2; ++rr) {
        const int r = warp * 2 + rr;
        float* lrow = s_lg + r * MM;
        // pass A: row max (pure fmax chains)
        float4 v0 = *(const float4*)&lrow[lane * 4];
        float ma = v0.x, mb = v0.y, mc = v0.z, md = v0.w;
#pragma unroll
        for (int k = 1; k < 8; ++k) {
            float4 v = *(const float4*)&lrow[lane * 4 + 128 * k];
            ma = fmaxf(ma, v.x); mb = fmaxf(mb, v.y);
            mc = fmaxf(mc, v.z); md = fmaxf(md, v.w);
        }
        float cl = fmaxf(fmaxf(ma, mb), fmaxf(mc, md));
#pragma unroll
        for (int off = 16; off; off >>= 1)
            cl = fmaxf(cl, __shfl_xor_sync(~0u, cl, off));
        // pass B: stats + argmax + w-write (single gumbels read)
        const float* grow = gum + (size_t)(n0 + r) * MM;
        float sa = 0, sb = 0, sc = 0, sd = 0;
        float Qa = 0, Qb = 0, Qc = 0, Qd = 0;
        float ca = -1e30f, cb = -1e30f, cc = -1e30f, cd = -1e30f;
        int bi = 0x7FFFFFFF;
#pragma unroll
        for (int k = 0; k < 8; ++k) {
            int m = lane * 4 + 128 * k;
            float4 l4 = *(const float4*)&lrow[m];
            float4 g4 = *(const float4*)&grow[m];
            float dxa = l4.x - cl, dxb = l4.y - cl, dxc = l4.z - cl, dxd = l4.w - cl;
            float ea = __expf(dxa), eb2 = __expf(dxb);
            float ec = __expf(dxc), ed = __expf(dxd);
            sa += ea; sb += eb2; sc += ec; sd += ed;
            Qa = fmaf(ea, dxa, Qa); Qb = fmaf(eb2, dxb, Qb);
            Qc = fmaf(ec, dxc, Qc); Qd = fmaf(ed, dxd, Qd);
            if (l4.x == cl) bi = min(bi, m);
            if (l4.y == cl) bi = min(bi, m + 1);
            if (l4.z == cl) bi = min(bi, m + 2);
            if (l4.w == cl) bi = min(bi, m + 3);
            float4 w4;
            w4.x = (l4.x + g4.x) * invT; w4.y = (l4.y + g4.y) * invT;
            w4.z = (l4.z + g4.z) * invT; w4.w = (l4.w + g4.w) * invT;
            ca = fmaxf(ca, w4.x); cb = fmaxf(cb, w4.y);
            cc = fmaxf(cc, w4.z); cd = fmaxf(cd, w4.w);
            *(float4*)&lrow[m] = w4;
        }
        float s2 = (sa + sb) + (sc + sd);
        float Q = (Qa + Qb) + (Qc + Qd);
        float cw = fmaxf(fmaxf(ca, cb), fmaxf(cc, cd));
#pragma unroll
        for (int off = 16; off; off >>= 1) {
            s2 += __shfl_xor_sync(~0u, s2, off);
            Q  += __shfl_xor_sync(~0u, Q, off);
            cw  = fmaxf(cw, __shfl_xor_sync(~0u, cw, off));
            bi  = min(bi, __shfl_xor_sync(~0u, bi, off));
        }
        if (lane == 0) {
            s_ent[r] = Q / s2 - __logf(s2);   // sum_m p*log p
            atomicAdd(&g_hist[bi], 1);
        }
        // pass C: ew = exp(w - cw); 1/s1 folded into GEMM2 epilogue
        float s1a = 0, s1b = 0, s1c = 0, s1d = 0;
#pragma unroll
        for (int k = 0; k < 8; ++k) {
            int m = lane * 4 + 128 * k;
            float4 w4 = *(const float4*)&lrow[m];
            w4.x = __expf(w4.x - cw); w4.y = __expf(w4.y - cw);
            w4.z = __expf(w4.z - cw); w4.w = __expf(w4.w - cw);
            s1a += w4.x; s1b += w4.y; s1c += w4.z; s1d += w4.w;
            *(float4*)&lrow[m] = w4;
        }
        float s1 = (s1a + s1b) + (s1c + s1d);
#pragma unroll
        for (int off = 16; off; off >>= 1) s1 += __shfl_xor_sync(~0u, s1, off);
        if (lane == 0) s_inv[r] = 1.0f / s1;
    }

    // ---- GEMM2: q = (ew @ e) * (1/s1)   (lane <-> d, m-halves split) ----
    const int rg2 = (warp & 3) * 8;
    const int dh = (warp >> 2) & 1;
    const int mh = warp >> 3;
    const int dcol = dh * 32 + lane;
    float qa[8] = {0, 0, 0, 0, 0, 0, 0, 0};
    for (int ch = 0; ch < NCH; ++ch) {
        float* eb = s_eb + (ch & 1) * (CHUNK * ES);
#pragma unroll
        for (int k = 0; k < 16; ++k) {
            int idx = tid + THREADS * k;
            eb[(idx >> 6) * ES + (idx & 63)] = pf[k];
        }
        if (ch + 1 < NCH) {
            const float* src = emb + (ch + 1) * (CHUNK * DD);
#pragma unroll
            for (int k = 0; k < 16; ++k) pf[k] = src[tid + THREADS * k];
        }
        __syncthreads();
#pragma unroll
        for (int mw = 0; mw < 16; ++mw) {
            int ml = mh * 64 + mw * 4;
            float e0 = eb[(ml + 0) * ES + dcol];
            float e1 = eb[(ml + 1) * ES + dcol];
            float e2v = eb[(ml + 2) * ES + dcol];
            float e3 = eb[(ml + 3) * ES + dcol];
#pragma unroll
            for (int r = 0; r < 8; ++r) {
                float4 p = *(const float4*)&s_lg[(rg2 + r) * MM + ch * CHUNK + ml];
                qa[r] = fmaf(p.w, e3, fmaf(p.z, e2v,
                          fmaf(p.y, e1, fmaf(p.x, e0, qa[r]))));
            }
        }
    }
#pragma unroll
    for (int r = 0; r < 8; ++r)
        s_q[(mh * ROWS + rg2 + r) * QS + dcol] = qa[r];
    __syncthreads();

    // ---- P5: combine halves, scale by 1/s1, write out, loss ----
    float myloss = 0.f;
#pragma unroll
    for (int i = tid; i < ROWS * DD; i += THREADS) {
        int r = i & 31, d = i >> 5;
        float q = (s_q[r * QS + d] + s_q[(ROWS + r) * QS + d]) * s_inv[r];
        out[(b * DD + d) * TT + t0 + r] = q;       // coalesced along r (== t)
        float dx = s_x[r * XS + d] - q;
        myloss = fmaf(dx, dx, myloss);
    }
    myloss *= hp;
    if (tid < ROWS) myloss += s_ent[tid];
#pragma unroll
    for (int off = 16; off; off >>= 1)
        myloss += __shfl_xor_sync(~0u, myloss, off);
    if (lane == 0) s_red[warp] = myloss;
    __syncthreads();
    if (tid == 0) {
        float t = 0.f;
#pragma unroll
        for (int w2 = 0; w2 < NWARP; ++w2) t += s_red[w2];
        g_partial[blockIdx.x] = t;
    }
}

// ---------------------------------------------------------------------------
__global__ void final_kernel(float* __restrict__ out, int out_size) {
    __shared__ float sl[32], sp[32];
    int tid = threadIdx.x;  // 1024 == NTILES == MM
    float v = g_partial[tid];
    float a = (float)g_hist[tid] * (1.0f / (float)NN);
    float pe = a * __logf(a + 1e-10f);
#pragma unroll
    for (int off = 16; off; off >>= 1) {
        v  += __shfl_xor_sync(~0u, v, off);
        pe += __shfl_xor_sync(~0u, pe, off);
    }
    if ((tid & 31) == 0) { sl[tid >> 5] = v; sp[tid >> 5] = pe; }
    __syncthreads();
    if (tid == 0) {
        float lv = 0.f, pv = 0.f;
#pragma unroll
        for (int i = 0; i < 32; ++i) { lv += sl[i]; pv += sp[i]; }
        if (out_size >= NN * DD + 2) {
            out[NN * DD]     = lv / (float)BB;
            out[NN * DD + 1] = __expf(-pv);
        }
    }
}

// ---------------------------------------------------------------------------
extern "C" void kernel_launch(void* const* d_in, const int* in_sizes, int n_in,
                              void* d_out, int out_size) {
    (void)in_sizes; (void)n_in;
    const float* x    = (const float*)d_in[0];
    const float* emb  = (const float*)d_in[1];
    const float* lvq  = (const float*)d_in[2];
    const float* gum  = (const float*)d_in[3];
    const float* temp = (const float*)d_in[4];
    float* out = (float*)d_out;

    cudaFuncSetAttribute(sqembed_main,
                         cudaFuncAttributeMaxDynamicSharedMemorySize, SMEM_BYTES);

    prep_kernel<<<MM / 8, 256>>>(emb);
    sqembed_main<<<NTILES, THREADS, SMEM_BYTES>>>(x, emb, lvq, gum, temp, out);
    final_kernel<<<1, 1024>>>(out, out_size);
}

// round 7
// speedup vs baseline: 1.9651x; 1.9651x over previous
#include <cuda_runtime.h>
#include <cuda_bf16.h>
#include <cstdint>

// SQEmbedding fused, mma.sync(bf16) edition. B=8,T=4096,D=64,M=1024,N=32768.
// Inputs: x(B,D,T) f32, embedding(M,D) f32, log_var_q f32[1], gumbels(N,M) f32,
//         temperature f32[1].  Output: quantized(B,D,T) + loss + perplexity.

#define BB 8
#define TT 4096
#define DD 64
#define MM 1024
#define NN (BB * TT)
#define ROWS 32
#define NTILES (NN / ROWS)      // 1024
#define THREADS 512
#define NWARP 16
#define NCH 8
#define CHK 128
#define LS 1028                  // s_lg f32 row stride (4-bank shift/row)

// smem byte offsets
#define SM_LG   0                // 32*1028*4 = 131584
#define SM_XH   131584           // x hi  [32][72] bf16 (144B rows)
#define SM_XL   136192           // x lo
#define SM_EBH  140800           // E chunk hi [128][72] bf16
#define SM_EBL  159232           // E chunk lo
#define SM_ECH  177664           // enc chunk hi [32][136] bf16 (272B rows)
#define SM_ECL  186368           // enc chunk lo
#define SM_X2   195072           // 32 f
#define SM_ENT  195200           // 32 f
#define SM_INV  195328           // 32 f
#define SM_RED  195456           // 16 f
#define SM_X2P  195520           // 512 f
#define SMEM_BYTES 197568

__device__ float g_e2[MM];
__device__ int   g_hist[MM];
__device__ float g_partial[NTILES];

// ---------------- helpers ----------------
__device__ __forceinline__ uint32_t smem_u32(const void* p) {
    uint32_t a;
    asm("{ .reg .u64 t; cvta.to.shared.u64 t, %1; cvt.u32.u64 %0, t; }"
        : "=r"(a) : "l"(p));
    return a;
}
__device__ __forceinline__ void ldsm4(uint32_t* r, uint32_t a) {
    asm volatile("ldmatrix.sync.aligned.m8n8.x4.shared.b16 {%0,%1,%2,%3}, [%4];"
                 : "=r"(r[0]), "=r"(r[1]), "=r"(r[2]), "=r"(r[3]) : "r"(a));
}
__device__ __forceinline__ void ldsm2(uint32_t& r0, uint32_t& r1, uint32_t a) {
    asm volatile("ldmatrix.sync.aligned.m8n8.x2.shared.b16 {%0,%1}, [%2];"
                 : "=r"(r0), "=r"(r1) : "r"(a));
}
__device__ __forceinline__ void ldsm2t(uint32_t& r0, uint32_t& r1, uint32_t a) {
    asm volatile("ldmatrix.sync.aligned.m8n8.x2.trans.shared.b16 {%0,%1}, [%2];"
                 : "=r"(r0), "=r"(r1) : "r"(a));
}
__device__ __forceinline__ void mma16816(float* d, const uint32_t* a,
                                         uint32_t b0, uint32_t b1) {
    asm volatile(
        "mma.sync.aligned.m16n8k16.row.col.f32.bf16.bf16.f32 "
        "{%0,%1,%2,%3}, {%4,%5,%6,%7}, {%8,%9}, {%0,%1,%2,%3};"
        : "+f"(d[0]), "+f"(d[1]), "+f"(d[2]), "+f"(d[3])
        : "r"(a[0]), "r"(a[1]), "r"(a[2]), "r"(a[3]), "r"(b0), "r"(b1));
}
__device__ __forceinline__ void bsplit(float v, unsigned short& h, unsigned short& l) {
    __nv_bfloat16 hb = __float2bfloat16(v);
    h = __bfloat16_as_ushort(hb);
    l = __bfloat16_as_ushort(__float2bfloat16(v - __bfloat162float(hb)));
}

// ---------------------------------------------------------------------------
__global__ void prep_norms(const float* __restrict__ emb) {
    int m = blockIdx.x * 8 + (threadIdx.x >> 5), lane = threadIdx.x & 31;
    if (m < MM) {
        float2 v = ((const float2*)(emb + m * DD))[lane];
        float s = fmaf(v.x, v.x, v.y * v.y);
#pragma unroll
        for (int o = 16; o; o >>= 1) s += __shfl_xor_sync(~0u, s, o);
        if (lane == 0) { g_e2[m] = s; g_hist[m] = 0; }
    }
}

// ---------------------------------------------------------------------------
__global__ __launch_bounds__(THREADS, 1)
void sqembed_main(const float* __restrict__ x,
                  const float* __restrict__ emb,
                  const float* __restrict__ lvq,
                  const float* __restrict__ gum,
                  const float* __restrict__ temp,
                  float* __restrict__ out) {
    extern __shared__ char smem[];
    float* s_lg  = (float*)(smem + SM_LG);
    float* s_x2  = (float*)(smem + SM_X2);
    float* s_ent = (float*)(smem + SM_ENT);
    float* s_inv = (float*)(smem + SM_INV);
    float* s_red = (float*)(smem + SM_RED);
    float* s_x2p = (float*)(smem + SM_X2P);

    const uint32_t sb = smem_u32(smem);
    const int tid = threadIdx.x, lane = tid & 31, warp = tid >> 5;
    const int n0 = blockIdx.x * ROWS, b = n0 / TT, t0 = n0 % TT;
    const float prec = __expf(-lvq[0]), hp = 0.5f * prec, invT = 1.0f / temp[0];
    const int mt = warp & 1;          // m-tile (16 rows)
    const int ng = warp >> 1;         // GEMM1: 16-code group; GEMM2: n-tile (8 d)

    // ---- load x, bf16-split, row-norm partials; prefetch E chunk 0 ----
    float x2p = 0.f;
#pragma unroll
    for (int k = 0; k < 4; ++k) {
        int i = tid + THREADS * k, r = i & 31, d = i >> 5;
        float v = x[(b * DD + d) * TT + t0 + r];
        unsigned short h, l;
        bsplit(v, h, l);
        *(unsigned short*)(smem + SM_XH + r * 144 + d * 2) = h;
        *(unsigned short*)(smem + SM_XL + r * 144 + d * 2) = l;
        x2p = fmaf(v, v, x2p);
    }
    s_x2p[warp * 32 + lane] = x2p;
    float2 pf2[8];
#pragma unroll
    for (int k = 0; k < 8; ++k) pf2[k] = ((const float2*)emb)[tid + THREADS * k];
    __syncthreads();
    if (tid < 32) {
        float s = 0.f;
#pragma unroll
        for (int k = 0; k < NWARP; ++k) s += s_x2p[k * 32 + tid];
        s_x2[tid] = s;
    }

    // ---- GEMM1 A fragments (x tile), held in regs for all chunks ----
    uint32_t ah[4][4], al[4][4];
    {
        uint32_t ax = sb + SM_XH + (mt * 16 + (lane & 15)) * 144 + ((lane >> 4) & 1) * 16;
#pragma unroll
        for (int ks = 0; ks < 4; ++ks) {
            ldsm4(ah[ks], ax + ks * 32);
            ldsm4(al[ks], ax + (SM_XL - SM_XH) + ks * 32);
        }
    }

    // ---- GEMM1: logits chunks of 128 codes ----
    const uint32_t bB = sb + SM_EBH + (ng * 16 + (lane & 7)) * 144 + ((lane >> 3) & 1) * 16;
    for (int ch = 0; ch < NCH; ++ch) {
        if (ch) __syncthreads();
#pragma unroll
        for (int k = 0; k < 8; ++k) {          // store E chunk hi/lo (pre-fetched f32)
            int j = tid + THREADS * k, code = j >> 5, dp = j & 31;
            unsigned short h0, l0, h1, l1;
            bsplit(pf2[k].x, h0, l0);
            bsplit(pf2[k].y, h1, l1);
            *(ushort2*)(smem + SM_EBH + code * 144 + dp * 4) = make_ushort2(h0, h1);
            *(ushort2*)(smem + SM_EBL + code * 144 + dp * 4) = make_ushort2(l0, l1);
        }
        if (ch + 1 < NCH) {
            const float2* src = (const float2*)(emb + (ch + 1) * CHK * DD);
#pragma unroll
            for (int k = 0; k < 8; ++k) pf2[k] = src[tid + THREADS * k];
        }
        __syncthreads();
        float acc[2][4] = {}, acb[2][4] = {};
#pragma unroll
        for (int ks = 0; ks < 4; ++ks) {
#pragma unroll
            for (int nt = 0; nt < 2; ++nt) {
                uint32_t bh0, bh1, bl0, bl1;
                ldsm2(bh0, bh1, bB + nt * 1152 + ks * 32);
                ldsm2(bl0, bl1, bB + 18432 + nt * 1152 + ks * 32);
                mma16816(acc[nt], ah[ks], bh0, bh1);
                mma16816(acb[nt], al[ks], bh0, bh1);
                mma16816(acb[nt], ah[ks], bl0, bl1);
            }
        }
        int gr = mt * 16 + (lane >> 2);
        float xx0 = s_x2[gr], xx1 = s_x2[gr + 8];
#pragma unroll
        for (int nt = 0; nt < 2; ++nt) {
            int code = ch * CHK + ng * 16 + nt * 8 + (lane & 3) * 2;
            float e20 = g_e2[code], e21 = g_e2[code + 1];
            *(float2*)&s_lg[gr * LS + code] = make_float2(
                prec * (acc[nt][0] + acb[nt][0]) - hp * (xx0 + e20),
                prec * (acc[nt][1] + acb[nt][1]) - hp * (xx0 + e21));
            *(float2*)&s_lg[(gr + 8) * LS + code] = make_float2(
                prec * (acc[nt][2] + acb[nt][2]) - hp * (xx1 + e20),
                prec * (acc[nt][3] + acb[nt][3]) - hp * (xx1 + e21));
        }
    }
    // prefetch chunk 0 again for GEMM2 (softmax hides it)
#pragma unroll
    for (int k = 0; k < 8; ++k) pf2[k] = ((const float2*)emb)[tid + THREADS * k];
    __syncthreads();

    // ---- softmax: warp owns rows 2w, 2w+1 ----
#pragma unroll 1
    for (int rr = 0; rr < 2; ++rr) {
        const int r = warp * 2 + rr;
        float* lrow = s_lg + r * LS;
        float4 v0 = *(const float4*)&lrow[lane * 4];
        float ma = v0.x, mb = v0.y, mc = v0.z, md = v0.w;
#pragma unroll
        for (int k = 1; k < 8; ++k) {
            float4 v = *(const float4*)&lrow[lane * 4 + 128 * k];
            ma = fmaxf(ma, v.x); mb = fmaxf(mb, v.y);
            mc = fmaxf(mc, v.z); md = fmaxf(md, v.w);
        }
        float cl = fmaxf(fmaxf(ma, mb), fmaxf(mc, md));
#pragma unroll
        for (int o = 16; o; o >>= 1) cl = fmaxf(cl, __shfl_xor_sync(~0u, cl, o));
        const float* grow = gum + (size_t)(n0 + r) * MM;
        float sa = 0, sbv = 0, sc = 0, sd = 0, Qa = 0, Qb = 0, Qc = 0, Qd = 0;
        float ca = -1e30f, cb = -1e30f, cc = -1e30f, cd = -1e30f;
        int bi = 0x7FFFFFFF;
#pragma unroll
        for (int k = 0; k < 8; ++k) {
            int m = lane * 4 + 128 * k;
            float4 l4 = *(const float4*)&lrow[m];
            float4 g4 = *(const float4*)&grow[m];
            float dxa = l4.x - cl, dxb = l4.y - cl, dxc = l4.z - cl, dxd = l4.w - cl;
            float ea = __expf(dxa), eb = __expf(dxb), ec = __expf(dxc), ed = __expf(dxd);
            sa += ea; sbv += eb; sc += ec; sd += ed;
            Qa = fmaf(ea, dxa, Qa); Qb = fmaf(eb, dxb, Qb);
            Qc = fmaf(ec, dxc, Qc); Qd = fmaf(ed, dxd, Qd);
            if (l4.x == cl) bi = min(bi, m);
            if (l4.y == cl) bi = min(bi, m + 1);
            if (l4.z == cl) bi = min(bi, m + 2);
            if (l4.w == cl) bi = min(bi, m + 3);
            float4 w4;
            w4.x = (l4.x + g4.x) * invT; w4.y = (l4.y + g4.y) * invT;
            w4.z = (l4.z + g4.z) * invT; w4.w = (l4.w + g4.w) * invT;
            ca = fmaxf(ca, w4.x); cb = fmaxf(cb, w4.y);
            cc = fmaxf(cc, w4.z); cd = fmaxf(cd, w4.w);
            *(float4*)&lrow[m] = w4;
        }
        float s2 = (sa + sbv) + (sc + sd), Q = (Qa + Qb) + (Qc + Qd);
        float cw = fmaxf(fmaxf(ca, cb), fmaxf(cc, cd));
#pragma unroll
        for (int o = 16; o; o >>= 1) {
            s2 += __shfl_xor_sync(~0u, s2, o);
            Q  += __shfl_xor_sync(~0u, Q, o);
            cw  = fmaxf(cw, __shfl_xor_sync(~0u, cw, o));
            bi  = min(bi, __shfl_xor_sync(~0u, bi, o));
        }
        if (lane == 0) {
            s_ent[r] = Q / s2 - __logf(s2);
            atomicAdd(&g_hist[bi], 1);
        }
        float s1a = 0, s1b = 0, s1c = 0, s1d = 0;
#pragma unroll
        for (int k = 0; k < 8; ++k) {
            int m = lane * 4 + 128 * k;
            float4 w4 = *(const float4*)&lrow[m];
            w4.x = __expf(w4.x - cw); w4.y = __expf(w4.y - cw);
            w4.z = __expf(w4.z - cw); w4.w = __expf(w4.w - cw);
            s1a += w4.x; s1b += w4.y; s1c += w4.z; s1d += w4.w;
            *(float4*)&lrow[m] = w4;
        }
        float s1 = (s1a + s1b) + (s1c + s1d);
#pragma unroll
        for (int o = 16; o; o >>= 1) s1 += __shfl_xor_sync(~0u, s1, o);
        if (lane == 0) s_inv[r] = 1.0f / s1;
    }

    // ---- GEMM2: q = enc @ E, chunks of 128 codes (same E tile, .trans B) ----
    float qa[4] = {}, qb[4] = {};
    const uint32_t aE = sb + SM_ECH + (mt * 16 + (lane & 15)) * 272 + ((lane >> 4) & 1) * 16;
    const uint32_t bE = sb + SM_EBH + (lane & 15) * 144 + ng * 16;
    for (int ch = 0; ch < NCH; ++ch) {
        __syncthreads();
#pragma unroll
        for (int k = 0; k < 8; ++k) {          // E chunk store (identical to GEMM1)
            int j = tid + THREADS * k, code = j >> 5, dp = j & 31;
            unsigned short h0, l0, h1, l1;
            bsplit(pf2[k].x, h0, l0);
            bsplit(pf2[k].y, h1, l1);
            *(ushort2*)(smem + SM_EBH + code * 144 + dp * 4) = make_ushort2(h0, h1);
            *(ushort2*)(smem + SM_EBL + code * 144 + dp * 4) = make_ushort2(l0, l1);
        }
#pragma unroll
        for (int k = 0; k < 4; ++k) {          // enc chunk f32 -> bf16 hi/lo
            int j = tid + THREADS * k, r = j >> 6, mp = j & 63;
            float2 v = *(const float2*)&s_lg[r * LS + ch * CHK + mp * 2];
            unsigned short h0, l0, h1, l1;
            bsplit(v.x, h0, l0);
            bsplit(v.y, h1, l1);
            *(ushort2*)(smem + SM_ECH + r * 272 + mp * 4) = make_ushort2(h0, h1);
            *(ushort2*)(smem + SM_ECL + r * 272 + mp * 4) = make_ushort2(l0, l1);
        }
        if (ch + 1 < NCH) {
            const float2* src = (const float2*)(emb + (ch + 1) * CHK * DD);
#pragma unroll
            for (int k = 0; k < 8; ++k) pf2[k] = src[tid + THREADS * k];
        }
        __syncthreads();
#pragma unroll
        for (int ks = 0; ks < 8; ++ks) {
            uint32_t eh[4], el[4], bh0, bh1, bl0, bl1;
            ldsm4(eh, aE + ks * 32);
            ldsm4(el, aE + (SM_ECL - SM_ECH) + ks * 32);
            ldsm2t(bh0, bh1, bE + ks * 2304);
            ldsm2t(bl0, bl1, bE + 18432 + ks * 2304);
            mma16816(qa, eh, bh0, bh1);
            mma16816(qb, el, bh0, bh1);
            mma16816(qb, eh, bl0, bl1);
        }
    }

    // ---- epilogue: scale by 1/s1, write out, loss ----
    const int gr = mt * 16 + (lane >> 2);
    const int d0 = ng * 8 + (lane & 3) * 2;
    float i0 = s_inv[gr], i1 = s_inv[gr + 8];
    float q00 = (qa[0] + qb[0]) * i0, q01 = (qa[1] + qb[1]) * i0;
    float q10 = (qa[2] + qb[2]) * i1, q11 = (qa[3] + qb[3]) * i1;
    out[(b * DD + d0) * TT + t0 + gr]         = q00;
    out[(b * DD + d0 + 1) * TT + t0 + gr]     = q01;
    out[(b * DD + d0) * TT + t0 + gr + 8]     = q10;
    out[(b * DD + d0 + 1) * TT + t0 + gr + 8] = q11;
    float myloss = 0.f;
#pragma unroll
    for (int i = 0; i < 4; ++i) {
        int r = (i < 2) ? gr : gr + 8;
        int d = d0 + (i & 1);
        float xh = __bfloat162float(__ushort_as_bfloat16(
            *(unsigned short*)(smem + SM_XH + r * 144 + d * 2)));
        float xl = __bfloat162float(__ushort_as_bfloat16(
            *(unsigned short*)(smem + SM_XL + r * 144 + d * 2)));
        float q = (i == 0) ? q00 : (i == 1) ? q01 : (i == 2) ? q10 : q11;
        float dx = (xh + xl) - q;
        myloss = fmaf(dx, dx, myloss);
    }
    myloss *= hp;
    if (tid < ROWS) myloss += s_ent[tid];
#pragma unroll
    for (int o = 16; o; o >>= 1) myloss += __shfl_xor_sync(~0u, myloss, o);
    if (lane == 0) s_red[warp] = myloss;
    __syncthreads();
    if (tid == 0) {
        float s = 0.f;
#pragma unroll
        for (int w2 = 0; w2 < NWARP; ++w2) s += s_red[w2];
        g_partial[blockIdx.x] = s;
    }
}

// ---------------------------------------------------------------------------
__global__ void final_kernel(float* __restrict__ out, int out_size) {
    __shared__ float sl[32], sp[32];
    int tid = threadIdx.x;
    float v = g_partial[tid];
    float a = (float)g_hist[tid] * (1.0f / (float)NN);
    float pe = a * __logf(a + 1e-10f);
#pragma unroll
    for (int o = 16; o; o >>= 1) {
        v  += __shfl_xor_sync(~0u, v, o);
        pe += __shfl_xor_sync(~0u, pe, o);
    }
    if ((tid & 31) == 0) { sl[tid >> 5] = v; sp[tid >> 5] = pe; }
    __syncthreads();
    if (tid == 0) {
        float lv = 0.f, pv = 0.f;
#pragma unroll
        for (int i = 0; i < 32; ++i) { lv += sl[i]; pv += sp[i]; }
        if (out_size >= NN * DD + 2) {
            out[NN * DD]     = lv / (float)BB;
            out[NN * DD + 1] = __expf(-pv);
        }
    }
}

// ---------------------------------------------------------------------------
extern "C" void kernel_launch(void* const* d_in, const int* in_sizes, int n_in,
                              void* d_out, int out_size) {
    (void)in_sizes; (void)n_in;
    const float* x    = (const float*)d_in[0];
    const float* emb  = (const float*)d_in[1];
    const float* lvq  = (const float*)d_in[2];
    const float* gum  = (const float*)d_in[3];
    const float* temp = (const float*)d_in[4];
    float* out = (float*)d_out;

    cudaFuncSetAttribute(sqembed_main,
                         cudaFuncAttributeMaxDynamicSharedMemorySize, SMEM_BYTES);

    prep_norms<<<MM / 8, 256>>>(emb);
    sqembed_main<<<NTILES, THREADS, SMEM_BYTES>>>(x, emb, lvq, gum, temp, out);
    final_kernel<<<1, 1024>>>(out, out_size);
}

// round 11
// speedup vs baseline: 2.2136x; 1.1265x over previous
#include <cuda_runtime.h>
#include <cuda_bf16.h>
#include <cstdint>

// SQEmbedding fused, mma.sync(bf16) + cp.async edition.
// B=8,T=4096,D=64,M=1024,N=32768.
#define BB 8
#define TT 4096
#define DD 64
#define MM 1024
#define NN (BB * TT)
#define ROWS 32
#define NTILES (NN / ROWS)      // 1024
#define THREADS 512
#define NWARP 16
#define NCH 8
#define CHK 128
#define LS 1028                  // s_lg f32 row stride

// smem byte offsets
#define SM_LG   0                // 32*1028*4 = 131584 (logits -> w)
#define SM_XH   131584           // x hi [32][72] bf16 (144B rows)
#define SM_XL   136192           // x lo
#define SM_EB   140800           // E tiles: 2 bufs x (hi 16K + lo 16K) = 64K
#define SM_ENC  206336           // enc hi 8K + lo 8K (swizzled 256B rows)
#define SM_X2   222720           // 32 f
#define SM_ENT  222848           // 32 f
#define SM_INV  222976           // 32 f
#define SM_RED  223104           // 16 f
#define SMEM_BYTES 223168

__device__ float g_e2[MM];
__device__ int   g_hist[MM];
__device__ float g_partial[NTILES];
__device__ __align__(16) __nv_bfloat16 g_eh[MM * DD];  // E bf16 hi, [code][d]
__device__ __align__(16) __nv_bfloat16 g_el[MM * DD];  // E bf16 lo

// ---------------- helpers ----------------
__device__ __forceinline__ uint32_t smem_u32(const void* p) {
    uint32_t a;
    asm("{ .reg .u64 t; cvta.to.shared.u64 t, %1; cvt.u32.u64 %0, t; }"
        : "=r"(a) : "l"(p));
    return a;
}
__device__ __forceinline__ void ldsm4(uint32_t* r, uint32_t a) {
    asm volatile("ldmatrix.sync.aligned.m8n8.x4.shared.b16 {%0,%1,%2,%3}, [%4];"
                 : "=r"(r[0]), "=r"(r[1]), "=r"(r[2]), "=r"(r[3]) : "r"(a));
}
__device__ __forceinline__ void ldsm2(uint32_t& r0, uint32_t& r1, uint32_t a) {
    asm volatile("ldmatrix.sync.aligned.m8n8.x2.shared.b16 {%0,%1}, [%2];"
                 : "=r"(r0), "=r"(r1) : "r"(a));
}
__device__ __forceinline__ void ldsm2t(uint32_t& r0, uint32_t& r1, uint32_t a) {
    asm volatile("ldmatrix.sync.aligned.m8n8.x2.trans.shared.b16 {%0,%1}, [%2];"
                 : "=r"(r0), "=r"(r1) : "r"(a));
}
__device__ __forceinline__ void mma16816(float* d, const uint32_t* a,
                                         uint32_t b0, uint32_t b1) {
    asm volatile(
        "mma.sync.aligned.m16n8k16.row.col.f32.bf16.bf16.f32 "
        "{%0,%1,%2,%3}, {%4,%5,%6,%7}, {%8,%9}, {%0,%1,%2,%3};"
        : "+f"(d[0]), "+f"(d[1]), "+f"(d[2]), "+f"(d[3])
        : "r"(a[0]), "r"(a[1]), "r"(a[2]), "r"(a[3]), "r"(b0), "r"(b1));
}
__device__ __forceinline__ void cpa16(uint32_t dst, const void* src) {
    asm volatile("cp.async.cg.shared.global [%0], [%1], 16;"
                 :: "r"(dst), "l"(src));
}
template <int N>
__device__ __forceinline__ void cpwait() {
    asm volatile("cp.async.wait_group %0;" :: "n"(N));
}
__device__ __forceinline__ void bsplit(float v, unsigned short& h, unsigned short& l) {
    __nv_bfloat16 hb = __float2bfloat16(v);
    h = __bfloat16_as_ushort(hb);
    l = __bfloat16_as_ushort(__float2bfloat16(v - __bfloat162float(hb)));
}
__device__ __forceinline__ uint32_t pack2(unsigned short a, unsigned short b) {
    return (uint32_t)a | ((uint32_t)b << 16);
}
// issue one E chunk (hi+lo) into buf via cp.async, swizzled 128B rows
__device__ __forceinline__ void issueE(uint32_t sb, int ch, int buf, int tid) {
    const char* bh = (const char*)g_eh + ch * 16384;
    const char* bl = (const char*)g_el + ch * 16384;
    uint32_t base = sb + SM_EB + buf * 32768;
#pragma unroll
    for (int u = 0; u < 2; ++u) {
        int t = tid + u * 512;              // granule 0..1023
        int row = t >> 3, col = t & 7;
        uint32_t off = row * 128 + ((col ^ (row & 7)) << 4);
        cpa16(base + off,         bh + row * 128 + col * 16);
        cpa16(base + 16384 + off, bl + row * 128 + col * 16);
    }
    asm volatile("cp.async.commit_group;");
}

// ---------------------------------------------------------------------------
// Prep: E bf16 hi/lo split, squared norms, histogram zero.
__global__ void prep_all(const float* __restrict__ emb) {
    __shared__ float sred[16];
    int tid = threadIdx.x;
    int idx = blockIdx.x * 512 + tid;       // 128 blocks x 512 = 65536
    float v = emb[idx];
    __nv_bfloat16 h = __float2bfloat16(v);
    g_eh[idx] = h;
    g_el[idx] = __float2bfloat16(v - __bfloat162float(h));
    float s = v * v;
#pragma unroll
    for (int o = 16; o; o >>= 1) s += __shfl_xor_sync(~0u, s, o);
    if ((tid & 31) == 0) sred[tid >> 5] = s;
    __syncthreads();
    if (tid < 8) {
        g_e2[blockIdx.x * 8 + tid] = sred[2 * tid] + sred[2 * tid + 1];
        g_hist[blockIdx.x * 8 + tid] = 0;
    }
}

// ---------------------------------------------------------------------------
__global__ __launch_bounds__(THREADS, 1)
void sqembed_main(const float* __restrict__ x,
                  const float* __restrict__ lvq,
                  const float* __restrict__ gum,
                  const float* __restrict__ temp,
                  float* __restrict__ out) {
    extern __shared__ char smem[];
    float* s_lg  = (float*)(smem + SM_LG);
    float* s_x2  = (float*)(smem + SM_X2);
    float* s_ent = (float*)(smem + SM_ENT);
    float* s_inv = (float*)(smem + SM_INV);
    float* s_red = (float*)(smem + SM_RED);
    float* s_x2p = (float*)(smem + SM_LG);   // alias: used before s_lg is written

    const uint32_t sb = smem_u32(smem);
    const int tid = threadIdx.x, lane = tid & 31, warp = tid >> 5;
    const int n0 = blockIdx.x * ROWS, b = n0 / TT, t0 = n0 % TT;
    const float prec = __expf(-lvq[0]), hp = 0.5f * prec, invT = 1.0f / temp[0];
    const int mt = warp & 1;
    const int ng = warp >> 1;

    // kick off E chunks 0 and 1 immediately
    issueE(sb, 0, 0, tid);
    issueE(sb, 1, 1, tid);

    // ---- load x, bf16-split (144B-row tiles), row-norm partials ----
    float x2p = 0.f;
#pragma unroll
    for (int k = 0; k < 4; ++k) {
        int i = tid + THREADS * k, r = i & 31, d = i >> 5;
        float v = x[(b * DD + d) * TT + t0 + r];
        unsigned short h, l;
        bsplit(v, h, l);
        *(unsigned short*)(smem + SM_XH + r * 144 + d * 2) = h;
        *(unsigned short*)(smem + SM_XL + r * 144 + d * 2) = l;
        x2p = fmaf(v, v, x2p);
    }
    s_x2p[warp * 32 + lane] = x2p;
    __syncthreads();
    if (tid < 32) {
        float s = 0.f;
#pragma unroll
        for (int k = 0; k < NWARP; ++k) s += s_x2p[k * 32 + tid];
        s_x2[tid] = s;
    }

    // ---- GEMM1 A fragments (x tile) in registers ----
    uint32_t ah[4][4], al[4][4];
    {
        uint32_t ax = sb + SM_XH + (mt * 16 + (lane & 15)) * 144 + ((lane >> 4) & 1) * 16;
#pragma unroll
        for (int ks = 0; ks < 4; ++ks) {
            ldsm4(ah[ks], ax + ks * 32);
            ldsm4(al[ks], ax + (SM_XL - SM_XH) + ks * 32);
        }
    }

    // ---- GEMM1: logits, chunks of 128 codes, cp.async double-buffered ----
    const int rb1 = ng * 16 + (lane & 7);   // code row (nt adds 8)
    const int x7 = lane & 7;
    const int gc1 = (lane >> 3) & 1;
#pragma unroll 1
    for (int ch = 0; ch < NCH; ++ch) {
        if (ch == NCH - 1) cpwait<0>(); else cpwait<1>();
        __syncthreads();
        uint32_t eb = sb + SM_EB + (ch & 1) * 32768;
        float acc[2][4] = {}, acb[2][4] = {};
#pragma unroll
        for (int ks = 0; ks < 4; ++ks) {
#pragma unroll
            for (int nt = 0; nt < 2; ++nt) {
                uint32_t a0 = eb + (rb1 + nt * 8) * 128 + (((ks * 2 + gc1) ^ x7) << 4);
                uint32_t bh0, bh1, bl0, bl1;
                ldsm2(bh0, bh1, a0);
                ldsm2(bl0, bl1, a0 + 16384);
                mma16816(acc[nt], ah[ks], bh0, bh1);
                mma16816(acb[nt], al[ks], bh0, bh1);
                mma16816(acb[nt], ah[ks], bl0, bl1);
            }
        }
        int gr = mt * 16 + (lane >> 2);
        float xx0 = s_x2[gr], xx1 = s_x2[gr + 8];
#pragma unroll
        for (int nt = 0; nt < 2; ++nt) {
            int code = ch * CHK + ng * 16 + nt * 8 + (lane & 3) * 2;
            float2 e2 = *(const float2*)&g_e2[code];
            *(float2*)&s_lg[gr * LS + code] = make_float2(
                prec * (acc[nt][0] + acb[nt][0]) - hp * (xx0 + e2.x),
                prec * (acc[nt][1] + acb[nt][1]) - hp * (xx0 + e2.y));
            *(float2*)&s_lg[(gr + 8) * LS + code] = make_float2(
                prec * (acc[nt][2] + acb[nt][2]) - hp * (xx1 + e2.x),
                prec * (acc[nt][3] + acb[nt][3]) - hp * (xx1 + e2.y));
        }
        __syncthreads();
        if (ch + 2 < NCH) issueE(sb, ch + 2, ch & 1, tid);
    }
    // bufs now hold: buf0 = E6, buf1 = E7 (reused by GEMM2)

    // ---- softmax passes A+B: stats, argmax, w-write (gumbels read once) ----
    float cw0 = 0.f, cw1 = 0.f;
#pragma unroll 1
    for (int rr = 0; rr < 2; ++rr) {
        const int r = warp * 2 + rr;
        float* lrow = s_lg + r * LS;
        float4 v0 = *(const float4*)&lrow[lane * 4];
        float ma = v0.x, mb = v0.y, mc = v0.z, md = v0.w;
#pragma unroll
        for (int k = 1; k < 8; ++k) {
            float4 v = *(const float4*)&lrow[lane * 4 + 128 * k];
            ma = fmaxf(ma, v.x); mb = fmaxf(mb, v.y);
            mc = fmaxf(mc, v.z); md = fmaxf(md, v.w);
        }
        float cl = fmaxf(fmaxf(ma, mb), fmaxf(mc, md));
#pragma unroll
        for (int o = 16; o; o >>= 1) cl = fmaxf(cl, __shfl_xor_sync(~0u, cl, o));
        const float* grow = gum + (size_t)(n0 + r) * MM;
        float sa = 0, sbv = 0, sc = 0, sd = 0, Qa = 0, Qb = 0, Qc = 0, Qd = 0;
        float ca = -1e30f, cb = -1e30f, cc = -1e30f, cd = -1e30f;
        int bi = 0x7FFFFFFF;
#pragma unroll
        for (int k = 0; k < 8; ++k) {
            int m = lane * 4 + 128 * k;
            float4 l4 = *(const float4*)&lrow[m];
            float4 g4 = *(const float4*)&grow[m];
            float dxa = l4.x - cl, dxb = l4.y - cl, dxc = l4.z - cl, dxd = l4.w - cl;
            float ea = __expf(dxa), eb = __expf(dxb), ec = __expf(dxc), ed = __expf(dxd);
            sa += ea; sbv += eb; sc += ec; sd += ed;
            Qa = fmaf(ea, dxa, Qa); Qb = fmaf(eb, dxb, Qb);
            Qc = fmaf(ec, dxc, Qc); Qd = fmaf(ed, dxd, Qd);
            if (l4.x == cl) bi = min(bi, m);
            if (l4.y == cl) bi = min(bi, m + 1);
            if (l4.z == cl) bi = min(bi, m + 2);
            if (l4.w == cl) bi = min(bi, m + 3);
            float4 w4;
            w4.x = (l4.x + g4.x) * invT; w4.y = (l4.y + g4.y) * invT;
            w4.z = (l4.z + g4.z) * invT; w4.w = (l4.w + g4.w) * invT;
            ca = fmaxf(ca, w4.x); cb = fmaxf(cb, w4.y);
            cc = fmaxf(cc, w4.z); cd = fmaxf(cd, w4.w);
            *(float4*)&lrow[m] = w4;
        }
        float s2 = (sa + sbv) + (sc + sd), Q = (Qa + Qb) + (Qc + Qd);
        float cw = fmaxf(fmaxf(ca, cb), fmaxf(cc, cd));
#pragma unroll
        for (int o = 16; o; o >>= 1) {
            s2 += __shfl_xor_sync(~0u, s2, o);
            Q  += __shfl_xor_sync(~0u, Q, o);
            cw  = fmaxf(cw, __shfl_xor_sync(~0u, cw, o));
            bi  = min(bi, __shfl_xor_sync(~0u, bi, o));
        }
        if (lane == 0) {
            s_ent[r] = Q / s2 - __logf(s2);
            atomicAdd(&g_hist[bi], 1);
        }
        if (rr == 0) cw0 = cw; else cw1 = cw;
    }
    __syncthreads();   // all w values in place before enc conversion

    // ---- GEMM2 (chunks 7..0): fused exp->bf16 conv + MMA ----
    float qa[4] = {}, qb[4] = {};
    float rs1 = 0.f;
    const int rowA = mt * 16 + (lane & 15);
    const int rcv = 2 * warp + (lane >> 4);           // conv row of this lane
    const uint32_t encw = sb + SM_ENC + rcv * 256 + (((lane & 15) ^ (rcv & 7)) << 4);
    const uint32_t bxor = (uint32_t)((ng ^ (lane & 7)) << 4);
#pragma unroll 1
    for (int it = 0; it < NCH; ++it) {
        const int ch = NCH - 1 - it;
        // convert enc chunk: each lane does 1 row x 8 codes
        {
            float cw = (lane >> 4) ? cw1 : cw0;
            const float* wr = s_lg + rcv * LS + ch * CHK + (lane & 15) * 8;
            float4 wa = *(const float4*)wr;
            float4 wb = *(const float4*)(wr + 4);
            float e0 = __expf(wa.x - cw), e1 = __expf(wa.y - cw);
            float e2 = __expf(wa.z - cw), e3 = __expf(wa.w - cw);
            float e4 = __expf(wb.x - cw), e5 = __expf(wb.y - cw);
            float e6 = __expf(wb.z - cw), e7 = __expf(wb.w - cw);
            rs1 += ((e0 + e1) + (e2 + e3)) + ((e4 + e5) + (e6 + e7));
            unsigned short h[8], l[8];
            bsplit(e0, h[0], l[0]); bsplit(e1, h[1], l[1]);
            bsplit(e2, h[2], l[2]); bsplit(e3, h[3], l[3]);
            bsplit(e4, h[4], l[4]); bsplit(e5, h[5], l[5]);
            bsplit(e6, h[6], l[6]); bsplit(e7, h[7], l[7]);
            uint4 hv = make_uint4(pack2(h[0], h[1]), pack2(h[2], h[3]),
                                  pack2(h[4], h[5]), pack2(h[6], h[7]));
            uint4 lv = make_uint4(pack2(l[0], l[1]), pack2(l[2], l[3]),
                                  pack2(l[4], l[5]), pack2(l[6], l[7]));
            *(uint4*)(smem + (encw - sb)) = hv;
            *(uint4*)(smem + (encw - sb) + 8192) = lv;
        }
        if (ch == 0) cpwait<0>(); else if (ch <= 5) cpwait<1>();
        __syncthreads();   // enc visible + E(ch) visible
        uint32_t eb = sb + SM_EB + (ch & 1) * 32768;
#pragma unroll
        for (int ks = 0; ks < 8; ++ks) {
            uint32_t aa = sb + SM_ENC + rowA * 256 +
                          (((ks * 2 + ((lane >> 4) & 1)) ^ (lane & 7)) << 4);
            uint32_t eh4[4], el4[4], bh0, bh1, bl0, bl1;
            ldsm4(eh4, aa);
            ldsm4(el4, aa + 8192);
            uint32_t ba = eb + (ks * 16 + (lane & 15)) * 128 + bxor;
            ldsm2t(bh0, bh1, ba);
            ldsm2t(bl0, bl1, ba + 16384);
            mma16816(qa, eh4, bh0, bh1);
            mma16816(qb, el4, bh0, bh1);
            mma16816(qb, eh4, bl0, bl1);
        }
        __syncthreads();   // everyone done reading enc tile + E buf
        if (ch >= 2) issueE(sb, ch - 2, ch & 1, tid);
    }
    // s1 -> s_inv (reduce 16-lane groups; lanes 0 and 16 hold row sums)
#pragma unroll
    for (int o = 8; o; o >>= 1) rs1 += __shfl_down_sync(~0u, rs1, o, 16);
    if ((lane & 15) == 0) s_inv[rcv] = 1.0f / rs1;
    __syncthreads();

    // ---- epilogue: scale by 1/s1, write out, loss ----
    const int gr = mt * 16 + (lane >> 2);
    const int d0 = ng * 8 + (lane & 3) * 2;
    float i0 = s_inv[gr], i1 = s_inv[gr + 8];
    float q00 = (qa[0] + qb[0]) * i0, q01 = (qa[1] + qb[1]) * i0;
    float q10 = (qa[2] + qb[2]) * i1, q11 = (qa[3] + qb[3]) * i1;
    out[(b * DD + d0) * TT + t0 + gr]         = q00;
    out[(b * DD + d0 + 1) * TT + t0 + gr]     = q01;
    out[(b * DD + d0) * TT + t0 + gr + 8]     = q10;
    out[(b * DD + d0 + 1) * TT + t0 + gr + 8] = q11;
    float myloss = 0.f;
#pragma unroll
    for (int i = 0; i < 4; ++i) {
        int r = (i < 2) ? gr : gr + 8;
        int d = d0 + (i & 1);
        float xh = __bfloat162float(__ushort_as_bfloat16(
            *(unsigned short*)(smem + SM_XH + r * 144 + d * 2)));
        float xl = __bfloat162float(__ushort_as_bfloat16(
            *(unsigned short*)(smem + SM_XL + r * 144 + d * 2)));
        float q = (i == 0) ? q00 : (i == 1) ? q01 : (i == 2) ? q10 : q11;
        float dx = (xh + xl) - q;
        myloss = fmaf(dx, dx, myloss);
    }
    myloss *= hp;
    if (tid < ROWS) myloss += s_ent[tid];
#pragma unroll
    for (int o = 16; o; o >>= 1) myloss += __shfl_xor_sync(~0u, myloss, o);
    if (lane == 0) s_red[warp] = myloss;
    __syncthreads();
    if (tid == 0) {
        float s = 0.f;
#pragma unroll
        for (int w2 = 0; w2 < NWARP; ++w2) s += s_red[w2];
        g_partial[blockIdx.x] = s;
    }
}

// ---------------------------------------------------------------------------
__global__ void final_kernel(float* __restrict__ out, int out_size) {
    __shared__ float sl[32], sp[32];
    int tid = threadIdx.x;
    float v = g_partial[tid];
    float a = (float)g_hist[tid] * (1.0f / (float)NN);
    float pe = a * __logf(a + 1e-10f);
#pragma unroll
    for (int o = 16; o; o >>= 1) {
        v  += __shfl_xor_sync(~0u, v, o);
        pe += __shfl_xor_sync(~0u, pe, o);
    }
    if ((tid & 31) == 0) { sl[tid >> 5] = v; sp[tid >> 5] = pe; }
    __syncthreads();
    if (tid == 0) {
        float lv = 0.f, pv = 0.f;
#pragma unroll
        for (int i = 0; i < 32; ++i) { lv += sl[i]; pv += sp[i]; }
        if (out_size >= NN * DD + 2) {
            out[NN * DD]     = lv / (float)BB;
            out[NN * DD + 1] = __expf(-pv);
        }
    }
}

// ---------------------------------------------------------------------------
extern "C" void kernel_launch(void* const* d_in, const int* in_sizes, int n_in,
                              void* d_out, int out_size) {
    (void)in_sizes; (void)n_in;
    const float* x    = (const float*)d_in[0];
    const float* emb  = (const float*)d_in[1];
    const float* lvq  = (const float*)d_in[2];
    const float* gum  = (const float*)d_in[3];
    const float* temp = (const float*)d_in[4];
    float* out = (float*)d_out;

    cudaFuncSetAttribute(sqembed_main,
                         cudaFuncAttributeMaxDynamicSharedMemorySize, SMEM_BYTES);

    prep_all<<<128, 512>>>(emb);
    sqembed_main<<<NTILES, THREADS, SMEM_BYTES>>>(x, lvq, gum, temp, out);
    final_kernel<<<1, 1024>>>(out, out_size);
}

// round 12
// speedup vs baseline: 2.3467x; 1.0601x over previous
#include <cuda_runtime.h>
#include <cuda_bf16.h>
#include <cstdint>

// SQEmbedding fully-fused flash-style, mma.sync(bf16) + cp.async.
// B=8,T=4096,D=64,M=1024,N=32768.
#define BB 8
#define TT 4096
#define DD 64
#define MM 1024
#define NN (BB * TT)
#define ROWS 32
#define NTILES (NN / ROWS)      // 1024
#define THREADS 512
#define NWARP 16
#define NCH 8

// smem byte offsets
#define SM_EB   0                // 2 bufs x (Eh 16K + El 16K) = 65536
#define SM_XH   65536            // x hi [32][72] bf16 (144B rows)
#define SM_XL   70144            // x lo
#define SM_E2   74752            // 1024 f32
#define SM_X2   78848            // 32 f32
#define SM_LMX  78976            // [32][8] f32  per-warp logit max
#define SM_S2   80000            // [32][8] f32
#define SM_QS   81024            // [32][8] f32
#define SM_WMX  82048            // [32][8] f32  per-warp w max
#define SM_S1   83072            // [32][8] f32
#define SM_BI   84096            // [32][8] int
#define SM_FQ   85120            // [32][8] f32  q rescale factors
#define SM_ENT  86144            // 32 f32
#define SM_INV  86272            // 32 f32
#define SM_RED  86400            // 16 f32
#define SM_QR   86464            // [32][66] f32 = 8448 (also x2-partial scratch early)
#define SMEM_BYTES 94912

__device__ float g_e2[MM];
__device__ int   g_hist[MM];
__device__ float g_partial[NTILES];
__device__ __align__(16) __nv_bfloat16 g_eh[MM * DD];  // E bf16 hi, [code][d]
__device__ __align__(16) __nv_bfloat16 g_el[MM * DD];  // E bf16 lo

// ---------------- helpers ----------------
__device__ __forceinline__ uint32_t smem_u32(const void* p) {
    uint32_t a;
    asm("{ .reg .u64 t; cvta.to.shared.u64 t, %1; cvt.u32.u64 %0, t; }"
        : "=r"(a) : "l"(p));
    return a;
}
__device__ __forceinline__ void ldsm4(uint32_t* r, uint32_t a) {
    asm volatile("ldmatrix.sync.aligned.m8n8.x4.shared.b16 {%0,%1,%2,%3}, [%4];"
                 : "=r"(r[0]), "=r"(r[1]), "=r"(r[2]), "=r"(r[3]) : "r"(a));
}
__device__ __forceinline__ void ldsm2(uint32_t& r0, uint32_t& r1, uint32_t a) {
    asm volatile("ldmatrix.sync.aligned.m8n8.x2.shared.b16 {%0,%1}, [%2];"
                 : "=r"(r0), "=r"(r1) : "r"(a));
}
__device__ __forceinline__ void ldsm2t(uint32_t& r0, uint32_t& r1, uint32_t a) {
    asm volatile("ldmatrix.sync.aligned.m8n8.x2.trans.shared.b16 {%0,%1}, [%2];"
                 : "=r"(r0), "=r"(r1) : "r"(a));
}
__device__ __forceinline__ void mma16816(float* d, const uint32_t* a,
                                         uint32_t b0, uint32_t b1) {
    asm volatile(
        "mma.sync.aligned.m16n8k16.row.col.f32.bf16.bf16.f32 "
        "{%0,%1,%2,%3}, {%4,%5,%6,%7}, {%8,%9}, {%0,%1,%2,%3};"
        : "+f"(d[0]), "+f"(d[1]), "+f"(d[2]), "+f"(d[3])
        : "r"(a[0]), "r"(a[1]), "r"(a[2]), "r"(a[3]), "r"(b0), "r"(b1));
}
__device__ __forceinline__ void cpa16(uint32_t dst, const void* src) {
    asm volatile("cp.async.cg.shared.global [%0], [%1], 16;" :: "r"(dst), "l"(src));
}
template <int N>
__device__ __forceinline__ void cpwait() {
    asm volatile("cp.async.wait_group %0;" :: "n"(N));
}
__device__ __forceinline__ void bsplit(float v, unsigned short& h, unsigned short& l) {
    __nv_bfloat16 hb = __float2bfloat16(v);
    h = __bfloat16_as_ushort(hb);
    l = __bfloat16_as_ushort(__float2bfloat16(v - __bfloat162float(hb)));
}
__device__ __forceinline__ uint32_t pack2(unsigned short a, unsigned short b) {
    return (uint32_t)a | ((uint32_t)b << 16);
}
// one E chunk (hi+lo) into buf via cp.async, swizzled 128B rows
__device__ __forceinline__ void issueE(uint32_t sb, int ch, int buf, int tid) {
    const char* bh = (const char*)g_eh + ch * 16384;
    const char* bl = (const char*)g_el + ch * 16384;
    uint32_t base = sb + SM_EB + buf * 32768;
#pragma unroll
    for (int u = 0; u < 2; ++u) {
        int t = tid + u * 512;
        int row = t >> 3, col = t & 7;
        uint32_t off = row * 128 + ((col ^ (row & 7)) << 4);
        cpa16(base + off,         bh + row * 128 + col * 16);
        cpa16(base + 16384 + off, bl + row * 128 + col * 16);
    }
    asm volatile("cp.async.commit_group;");
}

// ---------------------------------------------------------------------------
__global__ void prep_all(const float* __restrict__ emb) {
    __shared__ float sred[16];
    int tid = threadIdx.x;
    int idx = blockIdx.x * 512 + tid;
    float v = emb[idx];
    __nv_bfloat16 h = __float2bfloat16(v);
    g_eh[idx] = h;
    g_el[idx] = __float2bfloat16(v - __bfloat162float(h));
    float s = v * v;
#pragma unroll
    for (int o = 16; o; o >>= 1) s += __shfl_xor_sync(~0u, s, o);
    if ((tid & 31) == 0) sred[tid >> 5] = s;
    __syncthreads();
    if (tid < 8) {
        g_e2[blockIdx.x * 8 + tid] = sred[2 * tid] + sred[2 * tid + 1];
        g_hist[blockIdx.x * 8 + tid] = 0;
    }
}

// ---------------------------------------------------------------------------
__global__ __launch_bounds__(THREADS, 1)
void sqembed_main(const float* __restrict__ x,
                  const float* __restrict__ lvq,
                  const float* __restrict__ gum,
                  const float* __restrict__ temp,
                  float* __restrict__ out) {
    extern __shared__ char smem[];
    float* s_e2  = (float*)(smem + SM_E2);
    float* s_x2  = (float*)(smem + SM_X2);
    float* s_lmx = (float*)(smem + SM_LMX);
    float* s_s2  = (float*)(smem + SM_S2);
    float* s_qs  = (float*)(smem + SM_QS);
    float* s_wmx = (float*)(smem + SM_WMX);
    float* s_s1  = (float*)(smem + SM_S1);
    int*   s_bi  = (int*)(smem + SM_BI);
    float* s_fq  = (float*)(smem + SM_FQ);
    float* s_ent = (float*)(smem + SM_ENT);
    float* s_inv = (float*)(smem + SM_INV);
    float* s_red = (float*)(smem + SM_RED);
    float* s_qr  = (float*)(smem + SM_QR);

    const uint32_t sb = smem_u32(smem);
    const int tid = threadIdx.x, lane = tid & 31, warp = tid >> 5;
    const int mt = warp & 1, ng = warp >> 1;
    const int n0 = blockIdx.x * ROWS, b = n0 / TT, t0 = n0 % TT;
    const float prec = __expf(-lvq[0]), hp = 0.5f * prec, invT = 1.0f / temp[0];

    issueE(sb, 0, 0, tid);
    issueE(sb, 1, 1, tid);

    // ---- x load, bf16-split, row-norm partials; e2 staging ----
    float x2p = 0.f;
#pragma unroll
    for (int k = 0; k < 4; ++k) {
        int i = tid + THREADS * k, r = i & 31, d = i >> 5;
        float v = x[(b * DD + d) * TT + t0 + r];
        unsigned short h, l;
        bsplit(v, h, l);
        *(unsigned short*)(smem + SM_XH + r * 144 + d * 2) = h;
        *(unsigned short*)(smem + SM_XL + r * 144 + d * 2) = l;
        x2p = fmaf(v, v, x2p);
    }
    s_qr[warp * 32 + lane] = x2p;          // scratch (before qred use)
    s_e2[tid] = g_e2[tid];
    s_e2[tid + 512] = g_e2[tid + 512];
    __syncthreads();
    if (tid < 32) {
        float s = 0.f;
#pragma unroll
        for (int k = 0; k < NWARP; ++k) s += s_qr[k * 32 + tid];
        s_x2[tid] = s;
    }

    // per-lane row ids (within CTA tile)
    const int r0 = mt * 16 + (lane >> 2), r1 = r0 + 8;
    const int x7 = lane & 7, gc1 = (lane >> 3) & 1;
    const int rb1 = ng * 16 + x7;
    const uint32_t ax = sb + SM_XH + (mt * 16 + (lane & 15)) * 144 + ((lane >> 4) & 1) * 16;

    // running per-row (2 rows/lane) stats + q accumulator
    float M[2]  = {-1e30f, -1e30f};
    float S2[2] = {0.f, 0.f};
    float Qe[2] = {0.f, 0.f};
    float CW[2] = {-1e30f, -1e30f};
    float S1[2] = {0.f, 0.f};
    int   BI[2] = {0x7fffffff, 0x7fffffff};
    float q[8][4] = {};

    // ================= fused chunk loop =================
#pragma unroll 1
    for (int ch = 0; ch < NCH; ++ch) {
        if (ch == NCH - 1) cpwait<0>(); else cpwait<1>();
        __syncthreads();
        const uint32_t eb = sb + SM_EB + (ch & 1) * 32768;

        // GEMM1: x (A) @ E^T (B) -> logits frags
        uint32_t ah[4][4], al[4][4];
#pragma unroll
        for (int ks = 0; ks < 4; ++ks) {
            ldsm4(ah[ks], ax + ks * 32);
            ldsm4(al[ks], ax + (SM_XL - SM_XH) + ks * 32);
        }
        float acc[2][4] = {}, acb[2][4] = {};
#pragma unroll
        for (int ks = 0; ks < 4; ++ks) {
#pragma unroll
            for (int nt = 0; nt < 2; ++nt) {
                uint32_t a0 = eb + (rb1 + nt * 8) * 128 + (((ks * 2 + gc1) ^ x7) << 4);
                uint32_t bh0, bh1, bl0, bl1;
                ldsm2(bh0, bh1, a0);
                ldsm2(bl0, bl1, a0 + 16384);
                mma16816(acc[nt], ah[ks], bh0, bh1);
                mma16816(acb[nt], al[ks], bh0, bh1);
                mma16816(acb[nt], ah[ks], bl0, bl1);
            }
        }
        // logits in regs
        const int cb = ch * 128 + ng * 16 + 2 * (lane & 3);
        float2 e2a = *(const float2*)&s_e2[cb];
        float2 e2b = *(const float2*)&s_e2[cb + 8];
        float X0 = s_x2[r0], X1 = s_x2[r1];
        float l[2][4];
        l[0][0] = prec * (acc[0][0] + acb[0][0]) - hp * (X0 + e2a.x);
        l[0][1] = prec * (acc[0][1] + acb[0][1]) - hp * (X0 + e2a.y);
        l[0][2] = prec * (acc[0][2] + acb[0][2]) - hp * (X1 + e2a.x);
        l[0][3] = prec * (acc[0][3] + acb[0][3]) - hp * (X1 + e2a.y);
        l[1][0] = prec * (acc[1][0] + acb[1][0]) - hp * (X0 + e2b.x);
        l[1][1] = prec * (acc[1][1] + acb[1][1]) - hp * (X0 + e2b.y);
        l[1][2] = prec * (acc[1][2] + acb[1][2]) - hp * (X1 + e2b.x);
        l[1][3] = prec * (acc[1][3] + acb[1][3]) - hp * (X1 + e2b.y);

        // gumbels (row, codes cb..cb+1, cb+8..cb+9) — 32B coalesced per 4-group
        const float* gp0 = gum + (size_t)(n0 + r0) * MM + cb;
        const float* gp1 = gum + (size_t)(n0 + r1) * MM + cb;
        float2 ga0 = *(const float2*)gp0, gb0 = *(const float2*)(gp0 + 8);
        float2 ga1 = *(const float2*)gp1, gb1 = *(const float2*)(gp1 + 8);
        float g[2][4] = {{ga0.x, ga0.y, gb0.x, gb0.y},
                         {ga1.x, ga1.y, gb1.x, gb1.y}};

        uint32_t ah2[4], al2[4];   // enc A-frags for GEMM2
#pragma unroll
        for (int rr = 0; rr < 2; ++rr) {
            float v0 = l[0][rr * 2], v1 = l[0][rr * 2 + 1];
            float v2 = l[1][rr * 2], v3 = l[1][rr * 2 + 1];
            // --- entropy softmax online (exact) ---
            float mloc = fmaxf(fmaxf(v0, v1), fmaxf(v2, v3));
            mloc = fmaxf(mloc, __shfl_xor_sync(~0u, mloc, 1));
            mloc = fmaxf(mloc, __shfl_xor_sync(~0u, mloc, 2));
            float Mn = fmaxf(M[rr], mloc);
            float d0 = v0 - Mn, d1 = v1 - Mn, d2 = v2 - Mn, d3 = v3 - Mn;
            float e0 = __expf(d0), e1 = __expf(d1), e2v = __expf(d2), e3 = __expf(d3);
            float sl = (e0 + e1) + (e2v + e3);
            float ql = fmaf(e0, d0, fmaf(e1, d1, fmaf(e2v, d2, e3 * d3)));
            sl += __shfl_xor_sync(~0u, sl, 1); sl += __shfl_xor_sync(~0u, sl, 2);
            ql += __shfl_xor_sync(~0u, ql, 1); ql += __shfl_xor_sync(~0u, ql, 2);
            float f = __expf(M[rr] - Mn);
            Qe[rr] = f * (Qe[rr] + (M[rr] - Mn) * S2[rr]) + ql;
            S2[rr] = f * S2[rr] + sl;
            // argmax (first-index) via exact equality
            int cand = 0x7fffffff;
            if (v3 == Mn) cand = cb + 9;
            if (v2 == Mn) cand = cb + 8;
            if (v1 == Mn) cand = cb + 1;
            if (v0 == Mn) cand = cb;
            cand = min(cand, __shfl_xor_sync(~0u, cand, 1));
            cand = min(cand, __shfl_xor_sync(~0u, cand, 2));
            BI[rr] = (Mn > M[rr]) ? cand : min(BI[rr], cand);
            M[rr] = Mn;
            // --- gumbel softmax online + q rescale ---
            float w0 = (v0 + g[rr][0]) * invT, w1 = (v1 + g[rr][1]) * invT;
            float w2 = (v2 + g[rr][2]) * invT, w3 = (v3 + g[rr][3]) * invT;
            float wl = fmaxf(fmaxf(w0, w1), fmaxf(w2, w3));
            wl = fmaxf(wl, __shfl_xor_sync(~0u, wl, 1));
            wl = fmaxf(wl, __shfl_xor_sync(~0u, wl, 2));
            float Cn = fmaxf(CW[rr], wl);
            float f1 = __expf(CW[rr] - Cn);
            float p0 = __expf(w0 - Cn), p1 = __expf(w1 - Cn);
            float p2 = __expf(w2 - Cn), p3 = __expf(w3 - Cn);
            float ps = (p0 + p1) + (p2 + p3);
            ps += __shfl_xor_sync(~0u, ps, 1); ps += __shfl_xor_sync(~0u, ps, 2);
            S1[rr] = S1[rr] * f1 + ps;
            CW[rr] = Cn;
#pragma unroll
            for (int t = 0; t < 8; ++t) {
                q[t][rr * 2] *= f1;
                q[t][rr * 2 + 1] *= f1;
            }
            // enc -> bf16 split -> A-frags (C-frag layout == A-frag layout)
            unsigned short h0, lo0, h1, lo1, h2, lo2, h3, lo3;
            bsplit(p0, h0, lo0); bsplit(p1, h1, lo1);
            bsplit(p2, h2, lo2); bsplit(p3, h3, lo3);
            ah2[rr]     = pack2(h0, h1);   // nt0 row rr
            ah2[rr + 2] = pack2(h2, h3);   // nt1 row rr
            al2[rr]     = pack2(lo0, lo1);
            al2[rr + 2] = pack2(lo2, lo3);
        }

        // GEMM2: q += enc (A) @ E chunk (B), k = warp's 16 codes, n = 64 d
#pragma unroll
        for (int t = 0; t < 8; ++t) {
            uint32_t ba = eb + (ng * 16 + (lane & 15)) * 128 + ((t ^ x7) << 4);
            uint32_t bh0, bh1, bl0, bl1;
            ldsm2t(bh0, bh1, ba);
            ldsm2t(bl0, bl1, ba + 16384);
            mma16816(q[t], ah2, bh0, bh1);
            mma16816(q[t], al2, bh0, bh1);
            mma16816(q[t], ah2, bl0, bl1);
        }
        __syncthreads();
        if (ch + 2 < NCH) issueE(sb, ch + 2, ch & 1, tid);
    }

    // ================= final merges =================
    if ((lane & 3) == 0) {
        int o0 = r0 * 8 + ng, o1 = r1 * 8 + ng;
        s_lmx[o0] = M[0];  s_lmx[o1] = M[1];
        s_s2[o0]  = S2[0]; s_s2[o1]  = S2[1];
        s_qs[o0]  = Qe[0]; s_qs[o1]  = Qe[1];
        s_wmx[o0] = CW[0]; s_wmx[o1] = CW[1];
        s_s1[o0]  = S1[0]; s_s1[o1]  = S1[1];
        s_bi[o0]  = BI[0]; s_bi[o1]  = BI[1];
    }
    __syncthreads();
    if (tid < 32) {
        int r = tid;
        float Mg = -1e30f, Wg = -1e30f;
#pragma unroll
        for (int w = 0; w < 8; ++w) {
            Mg = fmaxf(Mg, s_lmx[r * 8 + w]);
            Wg = fmaxf(Wg, s_wmx[r * 8 + w]);
        }
        float s2g = 0.f, qg = 0.f, s1g = 0.f;
        int big = 0x7fffffff;
#pragma unroll
        for (int w = 0; w < 8; ++w) {
            float dm = s_lmx[r * 8 + w] - Mg;
            float fw = __expf(dm);
            s2g += s_s2[r * 8 + w] * fw;
            qg  += (s_qs[r * 8 + w] + dm * s_s2[r * 8 + w]) * fw;
            if (s_lmx[r * 8 + w] == Mg) big = min(big, s_bi[r * 8 + w]);
            float fq = __expf(s_wmx[r * 8 + w] - Wg);
            s1g += s_s1[r * 8 + w] * fq;
            s_fq[r * 8 + w] = fq;
        }
        s_ent[r] = qg / s2g - __logf(s2g);
        s_inv[r] = 1.0f / s1g;
        atomicAdd(&g_hist[big], 1);
    }
    __syncthreads();

    // deterministic ordered q reduction across the 8 ng warps
#pragma unroll 1
    for (int s = 0; s < 8; ++s) {
        if (ng == s) {
            float f0 = s_fq[r0 * 8 + ng], f1v = s_fq[r1 * 8 + ng];
            if (s == 0) {
#pragma unroll
                for (int t = 0; t < 8; ++t) {
                    int c = t * 8 + 2 * (lane & 3);
                    s_qr[r0 * 66 + c]     = q[t][0] * f0;
                    s_qr[r0 * 66 + c + 1] = q[t][1] * f0;
                    s_qr[r1 * 66 + c]     = q[t][2] * f1v;
                    s_qr[r1 * 66 + c + 1] = q[t][3] * f1v;
                }
            } else {
#pragma unroll
                for (int t = 0; t < 8; ++t) {
                    int c = t * 8 + 2 * (lane & 3);
                    s_qr[r0 * 66 + c]     += q[t][0] * f0;
                    s_qr[r0 * 66 + c + 1] += q[t][1] * f0;
                    s_qr[r1 * 66 + c]     += q[t][2] * f1v;
                    s_qr[r1 * 66 + c + 1] += q[t][3] * f1v;
                }
            }
        }
        __syncthreads();
    }

    // ---- epilogue: scale, write out, loss ----
    float myloss = 0.f;
#pragma unroll
    for (int k = 0; k < 4; ++k) {
        int i = tid + THREADS * k, r = i & 31, d = i >> 5;
        float qv = s_qr[r * 66 + d] * s_inv[r];
        out[(b * DD + d) * TT + t0 + r] = qv;
        float xh = __bfloat162float(__ushort_as_bfloat16(
            *(unsigned short*)(smem + SM_XH + r * 144 + d * 2)));
        float xl = __bfloat162float(__ushort_as_bfloat16(
            *(unsigned short*)(smem + SM_XL + r * 144 + d * 2)));
        float dx = (xh + xl) - qv;
        myloss = fmaf(dx, dx, myloss);
    }
    myloss *= hp;
    if (tid < ROWS) myloss += s_ent[tid];
#pragma unroll
    for (int o = 16; o; o >>= 1) myloss += __shfl_xor_sync(~0u, myloss, o);
    if (lane == 0) s_red[warp] = myloss;
    __syncthreads();
    if (tid == 0) {
        float s = 0.f;
#pragma unroll
        for (int w2 = 0; w2 < NWARP; ++w2) s += s_red[w2];
        g_partial[blockIdx.x] = s;
    }
}

// ---------------------------------------------------------------------------
__global__ void final_kernel(float* __restrict__ out, int out_size) {
    __shared__ float sl[32], sp[32];
    int tid = threadIdx.x;
    float v = g_partial[tid];
    float a = (float)g_hist[tid] * (1.0f / (float)NN);
    float pe = a * __logf(a + 1e-10f);
#pragma unroll
    for (int o = 16; o; o >>= 1) {
        v  += __shfl_xor_sync(~0u, v, o);
        pe += __shfl_xor_sync(~0u, pe, o);
    }
    if ((tid & 31) == 0) { sl[tid >> 5] = v; sp[tid >> 5] = pe; }
    __syncthreads();
    if (tid == 0) {
        float lv = 0.f, pv = 0.f;
#pragma unroll
        for (int i = 0; i < 32; ++i) { lv += sl[i]; pv += sp[i]; }
        if (out_size >= NN * DD + 2) {
            out[NN * DD]     = lv / (float)BB;
            out[NN * DD + 1] = __expf(-pv);
        }
    }
}

// ---------------------------------------------------------------------------
extern "C" void kernel_launch(void* const* d_in, const int* in_sizes, int n_in,
                              void* d_out, int out_size) {
    (void)in_sizes; (void)n_in;
    const float* x    = (const float*)d_in[0];
    const float* emb  = (const float*)d_in[1];
    const float* lvq  = (const float*)d_in[2];
    const float* gum  = (const float*)d_in[3];
    const float* temp = (const float*)d_in[4];
    float* out = (float*)d_out;

    cudaFuncSetAttribute(sqembed_main,
                         cudaFuncAttributeMaxDynamicSharedMemorySize, SMEM_BYTES);

    prep_all<<<128, 512>>>(emb);
    sqembed_main<<<NTILES, THREADS, SMEM_BYTES>>>(x, lvq, gum, temp, out);
    final_kernel<<<1, 1024>>>(out, out_size);
}